// round 13
// baseline (speedup 1.0000x reference)
#include <cuda_runtime.h>
#include <cuda_bf16.h>
#include <math.h>
#include <stdint.h>

#define TT 256
#define BB 128
#define FF 256
#define HH 512
#define G4H 2048
#define FQ 64
#define HQ 128
#define NR 64
#define MTOT (TT * BB)

// ---------------- scratch (device globals) -----------------------------------
__device__ float g_pre[(size_t)TT * BB * G4H];               // 268 MB
__device__ __nv_bfloat16 g_xHi[(size_t)MTOT * FF];           // 16 MB
__device__ __nv_bfloat16 g_xLo[(size_t)MTOT * FF];
__device__ __nv_bfloat16 g_KxT_Hi[G4H * FF];                 // [n=g*H+h][k=f]
__device__ __nv_bfloat16 g_KxT_Lo[G4H * FF];
__device__ __nv_bfloat16 g_KuHi[G4H * HH];                   // [col=h*4+g][k]
__device__ __nv_bfloat16 g_KuLo[G4H * HH];
__device__ __nv_bfloat16 g_fwHi[FF * HH];                    // [n=f][k=h]
__device__ __nv_bfloat16 g_fwLo[FF * HH];
__device__ __nv_bfloat16 g_hsHi[(size_t)(TT + 1) * BB * HH]; // slot t = h_{t-1}
__device__ __nv_bfloat16 g_hsLo[(size_t)(TT + 1) * BB * HH];
__device__ unsigned g_bar[TT];

__constant__ int   c_comp[16] = {0,1,2,3, 1,0,3,2, 2,3,0,1, 3,2,1,0};
__constant__ float c_sign[16] = {1,1,1,1, -1,1,1,-1, -1,-1,1,1, -1,1,-1,1};

__device__ __forceinline__ uint32_t smem_u32(const void* p) {
    uint32_t a;
    asm("{ .reg .u64 t; cvta.to.shared.u64 t, %1; cvt.u32.u64 %0, t; }" : "=r"(a) : "l"(p));
    return a;
}
#define LDSM4(r0, r1, r2, r3, a) \
    asm volatile("ldmatrix.sync.aligned.m8n8.x4.shared.b16 {%0,%1,%2,%3}, [%4];" \
                 : "=r"(r0), "=r"(r1), "=r"(r2), "=r"(r3) : "r"(a))
#define MMA16816(c, a, b) \
    asm volatile("mma.sync.aligned.m16n8k16.row.col.f32.bf16.bf16.f32 " \
                 "{%0,%1,%2,%3}, {%4,%5,%6,%7}, {%8,%9}, {%0,%1,%2,%3};" \
                 : "+f"((c)[0]), "+f"((c)[1]), "+f"((c)[2]), "+f"((c)[3]) \
                 : "r"((a)[0]), "r"((a)[1]), "r"((a)[2]), "r"((a)[3]), \
                   "r"((b)[0]), "r"((b)[1]))
#define CP16(sm, gp) asm volatile("cp.async.cg.shared.global [%0], [%1], 16;" :: "r"(sm), "l"(gp))
#define CP_COMMIT() asm volatile("cp.async.commit_group;" ::: "memory")
#define CP_WAIT0()  asm volatile("cp.async.wait_group 0;" ::: "memory")
#define CP_WAIT1()  asm volatile("cp.async.wait_group 1;" ::: "memory")

// ---------------- build Hamilton kernels + splits -----------------------------
__global__ void build_kernels(const float* __restrict__ Wx, const float* __restrict__ Uh) {
    int idx = blockIdx.x * blockDim.x + threadIdx.x;
    if (idx < G4H * FF) {             // KxT[n][k]
        int n = idx / FF, k = idx % FF;
        int g = n / HH, h = n % HH;
        int p = k / FQ, fi = k % FQ, q = h / HQ, hi = h % HQ;
        int c = c_comp[p * 4 + q];
        float v = c_sign[p * 4 + q] * Wx[((g * 4 + c) * FQ + fi) * HQ + hi];
        __nv_bfloat16 vh = __float2bfloat16(v);
        g_KxT_Hi[idx] = vh;
        g_KxT_Lo[idx] = __float2bfloat16(v - __bfloat162float(vh));
    }
    if (idx < G4H * HH) {             // Ku[col=h*4+g][k]
        int col = idx / HH, k = idx % HH;
        int h = col >> 2, g = col & 3;
        int p = k / HQ, ki = k % HQ, q = h / HQ, hi2 = h % HQ;
        int c = c_comp[p * 4 + q];
        float v = c_sign[p * 4 + q] * Uh[((g * 4 + c) * HQ + ki) * HQ + hi2];
        __nv_bfloat16 vh = __float2bfloat16(v);
        g_KuHi[idx] = vh;
        g_KuLo[idx] = __float2bfloat16(v - __bfloat162float(vh));
    }
}

__global__ void split_inputs(const float* __restrict__ x, const float* __restrict__ fw) {
    int idx = blockIdx.x * blockDim.x + threadIdx.x;
    if (idx < MTOT * FF) {
        float v = x[idx];
        __nv_bfloat16 vh = __float2bfloat16(v);
        g_xHi[idx] = vh;
        g_xLo[idx] = __float2bfloat16(v - __bfloat162float(vh));
    }
    if (idx < FF * HH) {
        float v = fw[idx];
        __nv_bfloat16 vh = __float2bfloat16(v);
        g_fwHi[idx] = vh;
        g_fwLo[idx] = __float2bfloat16(v - __bfloat162float(vh));
    }
    if (idx < BB * HH / 2) {          // zero slot 0 as u32 words
        ((uint32_t*)g_hsHi)[idx] = 0u;
        ((uint32_t*)g_hsLo)[idx] = 0u;
    }
    if (idx < TT) g_bar[idx] = 0u;
}

// ---------------- bf16x3 GEMM body: block 128m x 32n (unchanged from R12) -----
// SMEM: A 3 bufs x (16K hi + 16K lo) @0; B resident @98304 (hi, lo at +64*KTOT)
#define G_B 98304
#define GEMM_SMEM(KTOT) (G_B + 128 * (KTOT) + 1024)

#define GEMM_STAGE_A(c, buf) do {                                                 \
    _Pragma("unroll")                                                             \
    for (int i_ = 0; i_ < 4; i_++) {                                              \
        int row_ = sr + i_ * 32;                                                  \
        uint32_t off_ = (uint32_t)row_ * 128 + ((uint32_t)(su ^ (row_ & 7)) << 4);\
        CP16(sbu + (buf) * 32768 + off_,                                          \
             AHi + (size_t)(m0 + row_) * KTOT + (c) * 64 + su * 8);               \
        CP16(sbu + (buf) * 32768 + 16384 + off_,                                  \
             ALo + (size_t)(m0 + row_) * KTOT + (c) * 64 + su * 8);               \
    }                                                                             \
    CP_COMMIT();                                                                  \
} while (0)

template <int KTOT>
__device__ __forceinline__ void gemm_body(
    const __nv_bfloat16* __restrict__ AHi, const __nv_bfloat16* __restrict__ ALo,
    const __nv_bfloat16* __restrict__ BHi, const __nv_bfloat16* __restrict__ BLo,
    const float* __restrict__ bias, float* __restrict__ C, int N) {
    extern __shared__ char dsm[];
    char* sb = (char*)(((uintptr_t)dsm + 1023) & ~(uintptr_t)1023);
    const uint32_t sbu = smem_u32(sb);
    const int tid = threadIdx.x, wid = tid >> 5, lane = tid & 31;
    const int m0 = blockIdx.y * 128, n0g = blockIdx.x * 32;
    const int wm = (wid & 3) * 32, wn = (wid >> 2) * 16;
    const int sr = tid >> 3, su = tid & 7;

    // stage B resident: [32 n][KTOT k] hi/lo, swizzled
#pragma unroll
    for (int i = 0; i < KTOT / 64; i++) {
        int u = tid + 256 * i;
        int n = u / (KTOT / 8), s = u % (KTOT / 8);
        uint32_t off = (uint32_t)n * (2 * KTOT) + ((uint32_t)(s ^ (n & 7)) << 4);
        *(uint4*)(sb + G_B + off) = *(const uint4*)(BHi + (size_t)(n0g + n) * KTOT + s * 8);
        *(uint4*)(sb + G_B + 64 * KTOT + off) = *(const uint4*)(BLo + (size_t)(n0g + n) * KTOT + s * 8);
    }

    const int a_row_b = wm + (lane & 15), a_up = lane >> 4;
    const int b_n = wn + ((lane >> 4) << 3) + (lane & 7), b_kp = (lane >> 3) & 1;

    float acc[2][2][4] = {};
    GEMM_STAGE_A(0, 0);
    GEMM_STAGE_A(1, 1);
    __syncthreads();    // B resident ready (also covers A group ordering)

    const int NCH = KTOT / 64;
    for (int c = 0; c < NCH; c++) {
        const int buf = c % 3;
        if (c < NCH - 1) CP_WAIT1(); else CP_WAIT0();
        __syncthreads();
        if (c + 2 < NCH) GEMM_STAGE_A(c + 2, (c + 2) % 3);
#pragma unroll
        for (int ks = 0; ks < 4; ks++) {
            uint32_t ahi[2][4], alo[2][4], bhi[4], blo[4];
#pragma unroll
            for (int mt = 0; mt < 2; mt++) {
                int row = a_row_b + mt * 16;
                int u = ks * 2 + a_up;
                uint32_t off = (uint32_t)row * 128 + ((uint32_t)(u ^ (row & 7)) << 4);
                LDSM4(ahi[mt][0], ahi[mt][1], ahi[mt][2], ahi[mt][3], sbu + buf * 32768 + off);
                LDSM4(alo[mt][0], alo[mt][1], alo[mt][2], alo[mt][3], sbu + buf * 32768 + 16384 + off);
            }
            {
                int k8u = c * 8 + ks * 2 + b_kp;
                uint32_t off = (uint32_t)b_n * (2 * KTOT) + ((uint32_t)(k8u ^ (b_n & 7)) << 4);
                LDSM4(bhi[0], bhi[1], bhi[2], bhi[3], sbu + G_B + off);
                LDSM4(blo[0], blo[1], blo[2], blo[3], sbu + G_B + 64 * KTOT + off);
            }
            // term-major: break same-acc dependency chains
#pragma unroll
            for (int mt = 0; mt < 2; mt++)
#pragma unroll
                for (int nt = 0; nt < 2; nt++) MMA16816(acc[mt][nt], ahi[mt], bhi + nt * 2);
#pragma unroll
            for (int mt = 0; mt < 2; mt++)
#pragma unroll
                for (int nt = 0; nt < 2; nt++) MMA16816(acc[mt][nt], alo[mt], bhi + nt * 2);
#pragma unroll
            for (int mt = 0; mt < 2; mt++)
#pragma unroll
                for (int nt = 0; nt < 2; nt++) MMA16816(acc[mt][nt], ahi[mt], blo + nt * 2);
        }
    }

#pragma unroll
    for (int mt = 0; mt < 2; mt++)
#pragma unroll
        for (int nt = 0; nt < 2; nt++) {
            int r = m0 + wm + mt * 16 + (lane >> 2);
            int cc = n0g + wn + nt * 8 + 2 * (lane & 3);
            float b0 = bias[cc], b1 = bias[cc + 1];
            *(float2*)(C + (size_t)r * N + cc) =
                make_float2(acc[mt][nt][0] + b0, acc[mt][nt][1] + b1);
            *(float2*)(C + (size_t)(r + 8) * N + cc) =
                make_float2(acc[mt][nt][2] + b0, acc[mt][nt][3] + b1);
        }
}

__global__ void __launch_bounds__(256, 1) gemm_pre(const float* __restrict__ bx) {
    gemm_body<FF>(g_xHi, g_xLo, g_KxT_Hi, g_KxT_Lo, bx, g_pre, G4H);
}
__global__ void __launch_bounds__(256, 1) gemm_out(const float* __restrict__ fco_b,
                                                   float* __restrict__ out) {
    gemm_body<HH>(g_hsHi + (size_t)BB * HH, g_hsLo + (size_t)BB * HH,
                  g_fwHi, g_fwLo, fco_b, out, FF);
}

// ---------------- persistent mma.sync recurrence (2-stage, 128k chunks) -------
// 64 blocks x 256 thr. Block owns cols [32*bid, 32*bid+32) (col = h*4+g; 8 h).
// SMEM: KuHI 0(32K) KuLO 32768(32K) A @65536: 2 bufs x (32K hi + 32K lo),
//       HU @196608 (16K) -> 212992
#define R_BLO 32768
#define R_A   65536
#define R_HU  196608
#define SMEM_REC (212992 + 1024)

// chunk = 128 k (256 B per row); 16 CP16 per thread per chunk
#define REC_STAGE(c, buf) do {                                                    \
    _Pragma("unroll")                                                             \
    for (int i_ = 0; i_ < 8; i_++) {                                              \
        int row_ = sr + i_ * 16;                                                  \
        uint32_t off_ = (uint32_t)row_ * 256 + ((uint32_t)(su ^ (row_ & 7)) << 4);\
        CP16(sbu + R_A + (buf) * 65536 + off_,                                    \
             hHi + (size_t)row_ * HH + (c) * 128 + su * 8);                       \
        CP16(sbu + R_A + (buf) * 65536 + 32768 + off_,                            \
             hLo + (size_t)row_ * HH + (c) * 128 + su * 8);                       \
    }                                                                             \
    CP_COMMIT();                                                                  \
} while (0)

__global__ void __launch_bounds__(256, 1) qlstm_rec() {
    extern __shared__ char dsm[];
    char* sb = (char*)(((uintptr_t)dsm + 1023) & ~(uintptr_t)1023);
    float* hu = (float*)(sb + R_HU);                  // [32 col][128 b]
    const uint32_t sbu = smem_u32(sb);

    const int tid = threadIdx.x, wid = tid >> 5, lane = tid & 31, bid = blockIdx.x;
    const int col0 = bid * 32;
    const int m0 = (wid & 3) * 32;
    const int n0 = (wid >> 2) * 16;

    // stage Ku hi/lo once
    for (int i = 0; i < 8; i++) {
        int u = tid + 256 * i;
        int n = u >> 6, s = u & 63;
        uint32_t off = (uint32_t)n * 1024 + ((uint32_t)(s ^ (n & 7)) << 4);
        *(uint4*)(sb + off) = *(const uint4*)(g_KuHi + (size_t)(col0 + n) * HH + s * 8);
        *(uint4*)(sb + R_BLO + off) = *(const uint4*)(g_KuLo + (size_t)(col0 + n) * HH + s * 8);
    }
    __syncthreads();

    const int a_row_b = m0 + (lane & 15), a_up = lane >> 4;
    const int b_n = n0 + ((lane >> 4) << 3) + (lane & 7), b_kp = (lane >> 3) & 1;
    const int sr = tid >> 4, su = tid & 15;           // staging: 16 units/row

    const int eb = tid & 127, hq = tid >> 7;
    float cv[4] = {};
    const size_t hvec_off = (size_t)eb * HH + bid * 8 + hq * 4;

    for (int t = 0; t < TT; t++) {
        const __nv_bfloat16* __restrict__ hHi = g_hsHi + (size_t)t * BB * HH;
        const __nv_bfloat16* __restrict__ hLo = g_hsLo + (size_t)t * BB * HH;
        const float* __restrict__ pre_t = g_pre + (size_t)t * BB * G4H;

        float prf[4][4];
#pragma unroll
        for (int g = 0; g < 4; g++) {
            float4 v = __ldcg((const float4*)(pre_t + (size_t)eb * G4H + g * HH + bid * 8 + hq * 4));
            prf[g][0] = v.x; prf[g][1] = v.y; prf[g][2] = v.z; prf[g][3] = v.w;
        }

        float acc[2][2][4] = {};
        REC_STAGE(0, 0);
        for (int c = 0; c < 4; c++) {
            const int buf = c & 1;
            CP_WAIT0();
            __syncthreads();
            if (c < 3) REC_STAGE(c + 1, buf ^ 1);
#pragma unroll
            for (int ks = 0; ks < 8; ks++) {
                uint32_t ahi[2][4], alo[2][4], bhi[4], blo[4];
#pragma unroll
                for (int mt = 0; mt < 2; mt++) {
                    int row = a_row_b + mt * 16;
                    int u = ks * 2 + a_up;
                    uint32_t off = (uint32_t)row * 256 + ((uint32_t)(u ^ (row & 7)) << 4);
                    LDSM4(ahi[mt][0], ahi[mt][1], ahi[mt][2], ahi[mt][3],
                          sbu + R_A + buf * 65536 + off);
                    LDSM4(alo[mt][0], alo[mt][1], alo[mt][2], alo[mt][3],
                          sbu + R_A + buf * 65536 + 32768 + off);
                }
                {
                    int k8u = c * 16 + ks * 2 + b_kp;
                    uint32_t off = (uint32_t)b_n * 1024 + ((uint32_t)(k8u ^ (b_n & 7)) << 4);
                    LDSM4(bhi[0], bhi[1], bhi[2], bhi[3], sbu + off);
                    LDSM4(blo[0], blo[1], blo[2], blo[3], sbu + R_BLO + off);
                }
                // term-major: same-acc dep distance = 4 MMAs
#pragma unroll
                for (int mt = 0; mt < 2; mt++)
#pragma unroll
                    for (int nt = 0; nt < 2; nt++) MMA16816(acc[mt][nt], ahi[mt], bhi + nt * 2);
#pragma unroll
                for (int mt = 0; mt < 2; mt++)
#pragma unroll
                    for (int nt = 0; nt < 2; nt++) MMA16816(acc[mt][nt], alo[mt], bhi + nt * 2);
#pragma unroll
                for (int mt = 0; mt < 2; mt++)
#pragma unroll
                    for (int nt = 0; nt < 2; nt++) MMA16816(acc[mt][nt], ahi[mt], blo + nt * 2);
            }
            __syncthreads();
        }

        // dump C fragments to hu[col][b]
#pragma unroll
        for (int mt = 0; mt < 2; mt++)
#pragma unroll
            for (int nt = 0; nt < 2; nt++) {
                int row = m0 + mt * 16 + (lane >> 2);
                int col = n0 + nt * 8 + 2 * (lane & 3);
                hu[col * 128 + row]           = acc[mt][nt][0];
                hu[(col + 1) * 128 + row]     = acc[mt][nt][1];
                hu[col * 128 + row + 8]       = acc[mt][nt][2];
                hu[(col + 1) * 128 + row + 8] = acc[mt][nt][3];
            }
        __syncthreads();

        {
            float hv[4];
#pragma unroll
            for (int j = 0; j < 4; j++) {
                int cl = (hq * 4 + j) * 4;
                float f = prf[0][j] + hu[(cl + 0) * 128 + eb];
                float i = prf[1][j] + hu[(cl + 1) * 128 + eb];
                float o = prf[2][j] + hu[(cl + 2) * 128 + eb];
                float a = prf[3][j] + hu[(cl + 3) * 128 + eb];
                float ft = 1.0f / (1.0f + expf(-f));
                float it = 1.0f / (1.0f + expf(-i));
                float ot = 1.0f / (1.0f + expf(-o));
                float cc2 = it * tanhf(a) + ft * cv[j];
                cv[j] = cc2;
                hv[j] = ot * tanhf(cc2);
            }
            uint32_t hp[2], lp[2];
#pragma unroll
            for (int q = 0; q < 2; q++) {
                __nv_bfloat16 b0 = __float2bfloat16(hv[2 * q]);
                __nv_bfloat16 b1 = __float2bfloat16(hv[2 * q + 1]);
                __nv_bfloat16 l0 = __float2bfloat16(hv[2 * q] - __bfloat162float(b0));
                __nv_bfloat16 l1 = __float2bfloat16(hv[2 * q + 1] - __bfloat162float(b1));
                hp[q] = (uint32_t)__bfloat16_as_ushort(b0) | ((uint32_t)__bfloat16_as_ushort(b1) << 16);
                lp[q] = (uint32_t)__bfloat16_as_ushort(l0) | ((uint32_t)__bfloat16_as_ushort(l1) << 16);
            }
            *(uint2*)(g_hsHi + (size_t)(t + 1) * BB * HH + hvec_off) = make_uint2(hp[0], hp[1]);
            *(uint2*)(g_hsLo + (size_t)(t + 1) * BB * HH + hvec_off) = make_uint2(lp[0], lp[1]);
        }

        __threadfence();
        __syncthreads();
        if (tid == 0) {
            unsigned done = atomicAdd(&g_bar[t], 1u) + 1u;
            while (done < (unsigned)NR) { __nanosleep(64); done = *(volatile unsigned*)&g_bar[t]; }
        }
        __syncthreads();
    }
}

// ---------------- launch ------------------------------------------------------
extern "C" void kernel_launch(void* const* d_in, const int* in_sizes, int n_in,
                              void* d_out, int out_size) {
    const float* x     = (const float*)d_in[0];
    const float* Wx    = (const float*)d_in[1];
    const float* bx    = (const float*)d_in[2];
    const float* Uh    = (const float*)d_in[3];
    const float* fco_w = (const float*)d_in[4];
    const float* fco_b = (const float*)d_in[5];
    float* out = (float*)d_out;

    cudaFuncSetAttribute(qlstm_rec, cudaFuncAttributeMaxDynamicSharedMemorySize, SMEM_REC);
    cudaFuncSetAttribute(gemm_pre, cudaFuncAttributeMaxDynamicSharedMemorySize, GEMM_SMEM(FF));
    cudaFuncSetAttribute(gemm_out, cudaFuncAttributeMaxDynamicSharedMemorySize, GEMM_SMEM(HH));

    build_kernels<<<4096, 256>>>(Wx, Uh);
    split_inputs<<<MTOT * FF / 256, 256>>>(x, fco_w);
    gemm_pre<<<dim3(G4H / 32, MTOT / 128), 256, GEMM_SMEM(FF)>>>(bx);
    qlstm_rec<<<NR, 256, SMEM_REC>>>();
    gemm_out<<<dim3(FF / 32, MTOT / 128), 256, GEMM_SMEM(HH)>>>(fco_b, out);
}